// round 14
// baseline (speedup 1.0000x reference)
#include <cuda_runtime.h>
#include <cuda_pipeline.h>
#include <math.h>
#include <float.h>

#define TT 5
#define CC 3
#define HH 384
#define WW 384
#define HW (HH*WW)
#define KK 10
#define NHH 96
#define NWW 96
#define NQ (TT*NHH*NWW)      /* 46080 */
#define WPB 4

/* private regions: rows [c0:16|c1:16|c2:16], row stride 52 floats (13 quads, odd) */
#define PRSTR 52
#define PCSTEP 16
#define PDI    780
/* shared di=1 region: rows [c0:28|c1:28|c2:28], stride 84 (21 quads, odd) */
#define SRSTR 84
#define SCSTEP 28
#define QSTR 8

typedef unsigned long long u64;

__device__ double       g_accum;
__device__ unsigned int g_count;

__device__ __forceinline__ void upk2(u64 v, float& lo, float& hi) {
    asm("mov.b64 {%0, %1}, %2;" : "=f"(lo), "=f"(hi) : "l"(v));
}
__device__ __forceinline__ void fma2(u64& d, u64 a, u64 b) {
    asm("fma.rn.f32x2 %0, %1, %2, %0;" : "+l"(d) : "l"(a), "l"(b));
}
#define CE(a,b) { unsigned lo_ = min(a,b), hi_ = max(a,b); a = lo_; b = hi_; }

__global__ void __launch_bounds__(32*WPB, 6)
fused_kernel(const float* __restrict__ vid,
             const float* __restrict__ fflow,
             const float* __restrict__ bflow,
             float* __restrict__ out, int out_size)
{
    __shared__ __align__(16) float s_region[WPB][2*PDI];   /* 6240B/warp */
    __shared__ __align__(16) float s_sh[15*SRSTR];         /* 5040B */
    __shared__ __align__(16) float s_qR[WPB][3*7*QSTR];    /* {q0..q6,0} */
    __shared__ __align__(16) float s_qL[WPB][3*7*QSTR];    /* {0,q0..q6} */
    __shared__ int   s_meta[WPB][12];

    const int tid  = threadIdx.x;
    const int warp = tid >> 5;
    const int lane = tid & 31;
    const int qidx = blockIdx.x * WPB + warp;

    const int ti = qidx / (NHH * NWW);
    const int rr = qidx - ti * (NHH * NWW);
    const int hi = (rr / NWW) * 4;
    const int wi = (rr % NWW) * 4;
    const int wi0 = wi - 4*warp;

    float* region = s_region[warp];
    float* qR     = s_qR[warp];
    float* qL     = s_qL[warp];
    int*   meta   = s_meta[warp];

    /* ---- meta per di (0: t-1/bflow, 1: t/zero, 2: t+1/fflow) ---- */
    if (lane < 3) {
        int di = lane;
        int tj, bh, bw;
        if (di == 1) { tj = ti; bh = hi; bw = wi; }
        else {
            const float* fl = (di == 0) ? bflow : fflow;
            tj = (di == 0) ? max(ti - 1, 0) : min(ti + 1, TT - 1);
            float fx = fl[((ti*2 + 0)*HH + hi)*WW + wi];
            float fy = fl[((ti*2 + 1)*HH + hi)*WW + wi];
            bh = min(max(hi + (int)rintf(fy), 0), HH - 1);
            bw = min(max(wi + (int)rintf(fx), 0), WW - 1);
        }
        meta[di*4 + 0] = tj;
        meta[di*4 + 1] = max(bh - 4, 0);
        meta[di*4 + 2] = bh;
        meta[di*4 + 3] = bw;
    }
    __syncwarp();

    /* ---- block-shared di=1 region: 15 rows x [3c x 28 cols]
           safe path: 16B cp.async (gmem base 16B-aligned: xsS mult of 4) ---- */
    {
        const int ysS = max(hi - 4, 0);
        const int xsS = max(wi0 - 4, 0);
        if (ysS <= HH-15 && xsS <= WW-28) {
            const float* src = vid + ti*3*HW + ysS*WW + xsS;
            if (tid < 105) {
                int row = tid / 7, ch = tid - (tid/7)*7;
                #pragma unroll
                for (int c = 0; c < 3; c++)
                    __pipeline_memcpy_async(s_sh + row*SRSTR + c*SCSTEP + ch*4,
                                            src + c*HW + row*WW + ch*4, 16);
            }
        } else {
            const int rx = tid & 31, r0 = tid >> 5;
            if (rx < 28) {
                #pragma unroll
                for (int c = 0; c < 3; c++) {
                    #pragma unroll
                    for (int k = 0; k < 4; k++) {
                        int r = r0 + 4*k;
                        if (r < 15) {
                            int y = min(ysS + r, HH-1);
                            int x = min(xsS + rx, WW-1);
                            s_sh[r*SRSTR + c*SCSTEP + rx] = vid[(ti*3 + c)*HW + y*WW + x];
                        }
                    }
                }
            }
        }
    }
    __pipeline_commit();   /* group A: s_sh */

    /* ---- per-warp regions di=0/di=2 (R10 lane map; safe path 4B cp.async) ---- */
    {
        const int ry = lane >> 4, rx = lane & 15;
        #pragma unroll
        for (int ds = 0; ds < 2; ds++) {
            const int di = ds*2;
            const int tj = meta[di*4 + 0];
            const int ys = meta[di*4 + 1];
            const int xs = max(meta[di*4 + 3] - 4, 0);
            float* dst0 = region + ds*PDI + ry*PRSTR + rx;
            if (ys <= HH-15 && xs <= WW-16) {
                const float* src0 = vid + tj*3*HW + (ys + ry)*WW + xs + rx;
                #pragma unroll
                for (int c = 0; c < 3; c++) {
                    const float* s2 = src0 + c*HW;
                    float* d2 = dst0 + c*PCSTEP;
                    #pragma unroll
                    for (int k = 0; k < 8; k++) {
                        if (ry + 2*k < 15)
                            __pipeline_memcpy_async(d2 + k*2*PRSTR, s2 + k*2*WW, 4);
                    }
                }
            } else {
                const float* src = vid + tj*3*HW;
                #pragma unroll
                for (int c = 0; c < 3; c++) {
                    #pragma unroll
                    for (int k = 0; k < 8; k++) {
                        int r = ry + 2*k;
                        if (r < 15) {
                            int y = min(ys + r, HH-1);
                            int x = min(xs + rx, WW-1);
                            region[ds*PDI + r*PRSTR + c*PCSTEP + rx] = src[c*HW + y*WW + x];
                        }
                    }
                }
            }
        }
    }
    __pipeline_commit();          /* group B: private */
    __pipeline_wait_prior(1);     /* s_sh complete */
    __syncthreads();              /* cross-warp visibility of s_sh */

    /* ---- query patch built from s_sh; Sum(q^2) (overlaps private staging) ---- */
    float qsq_part = 0.f;
    {
        const int rbase = min(hi, 4);
        const int cbase = wi - max(wi0 - 4, 0);
        #pragma unroll
        for (int k = 0; k < 6; k++) {
            int e = lane + 32*k;
            if (e < 168) {
                int row = e >> 3, px = e & 7;
                float val = 0.f;
                if (px < 7) {
                    int c = row / 7, py = row - (row/7)*7;
                    val = s_sh[(rbase + py)*SRSTR + c*SCSTEP + cbase + px];
                    qsq_part = fmaf(val, val, qsq_part);
                }
                qR[e] = val;
                qL[(row << 3) + ((px + 1) & 7)] = val;
            }
        }
    }
    #pragma unroll
    for (int off = 16; off; off >>= 1)
        qsq_part += __shfl_xor_sync(0xffffffffu, qsq_part, off);
    const float qs = qsq_part;
    __pipeline_wait_prior(0);     /* private regions complete (same-warp) */
    __syncwarp();

    float d[9];
    #pragma unroll
    for (int j = 0; j < 9; j++) d[j] = FLT_MAX;

    /* ---- lane remap: di-major groups of 8 -> phase-pure LDS.128 ---- */
    if (lane < 27) {
        const int di = (lane < 24) ? (lane >> 3) : (lane - 24);
        const int sy = (lane < 24) ? (lane & 7)  : 8;
        const int ys = meta[di*4 + 1];
        const int bh = meta[di*4 + 2];
        const int bw = meta[di*4 + 3];
        const int rowoff = min(max(bh - 4 + sy, 0), HH - 1) - ys;
        const int xsS = max(wi0 - 4, 0);
        const int xb  = (di == 1) ? xsS : max(bw - 4, 0);
        const int rstride = (di == 1) ? SRSTR : PRSTR;
        const int cstep   = (di == 1) ? SCSTEP : PCSTEP;
        const float* base = (di == 1) ? s_sh : region + (di == 0 ? 0 : PDI);
        const int xoff = max(bw - 4, 0) - xb;   /* 0 (private) or mult of 4 (di=1) */
        const bool fastx = (bw >= 4) && (bw <= WW - 11);

        if (fastx) {
            u64 acc[9], sq2[8];
            #pragma unroll
            for (int s = 0; s < 9; s++) acc[s] = 0ull;
            #pragma unroll
            for (int p = 0; p < 8; p++) sq2[p] = 0ull;

            const float* pb = base + rowoff*rstride + xoff;  /* 16B aligned */
            #pragma unroll
            for (int c = 0; c < 3; c++) {
                #pragma unroll
                for (int py = 0; py < 7; py++) {
                    const ulonglong2* vr = (const ulonglong2*)(pb + py*rstride + c*cstep);
                    ulonglong2 va = vr[0], vb = vr[1], vc = vr[2], vd = vr[3];
                    u64 ve[8] = {va.x, va.y, vb.x, vb.y, vc.x, vc.y, vd.x, vd.y};
                    const ulonglong2* qrv = (const ulonglong2*)(qR + (c*7 + py)*QSTR);
                    const ulonglong2* qlv = (const ulonglong2*)(qL + (c*7 + py)*QSTR);
                    ulonglong2 qa = qrv[0], qb = qrv[1];
                    ulonglong2 qc = qlv[0], qd = qlv[1];
                    u64 qe[4] = {qa.x, qa.y, qb.x, qb.y};
                    u64 qo[4] = {qc.x, qc.y, qd.x, qd.y};

                    #pragma unroll
                    for (int j = 0; j < 4; j++) {
                        #pragma unroll
                        for (int e2 = 0; e2 < 5; e2++)      /* sx = 0,2,4,6,8 */
                            fma2(acc[2*e2], qe[j], ve[e2 + j]);
                        #pragma unroll
                        for (int o = 0; o < 4; o++)         /* sx = 1,3,5,7 */
                            fma2(acc[2*o + 1], qo[j], ve[o + j]);
                    }
                    #pragma unroll
                    for (int p = 0; p < 8; p++) fma2(sq2[p], ve[p], ve[p]);
                }
            }

            float col[15];
            {
                float lo, hiv;
                #pragma unroll
                for (int p = 0; p < 7; p++) { upk2(sq2[p], lo, hiv); col[2*p] = lo; col[2*p+1] = hiv; }
                upk2(sq2[7], lo, hiv); col[14] = lo;
            }
            float pre[16]; pre[0] = 0.f;
            #pragma unroll
            for (int j = 0; j < 15; j++) pre[j+1] = pre[j] + col[j];
            #pragma unroll
            for (int sx = 0; sx < 9; sx++) {
                float alo, ahi; upk2(acc[sx], alo, ahi);
                float qv2 = alo + ahi;
                float vs = pre[sx+7] - pre[sx];
                d[sx] = fmaf(-2.f, qv2, qs + vs);
            }
        } else {
            /* rare x-border path */
            #pragma unroll
            for (int sx = 0; sx < 9; sx++) {
                int co = min(max(bw - 4 + sx, 0), WW - 1) - xb;
                float a = 0.f;
                for (int c = 0; c < 3; c++) {
                    for (int py = 0; py < 7; py++) {
                        const float* row = base + (rowoff + py)*rstride + c*cstep + co;
                        const float* qrow = qR + (c*7 + py)*QSTR;
                        #pragma unroll
                        for (int px = 0; px < 7; px++) {
                            float t = qrow[px] - row[px];
                            a = fmaf(t, t, a);
                        }
                    }
                }
                d[sx] = a;
            }
        }
    }

    /* ---- top-10: per-lane selection-sort network + shift-advance extract ---- */
    unsigned s0 = __float_as_uint(fmaxf(d[0], 0.f));
    unsigned s1 = __float_as_uint(fmaxf(d[1], 0.f));
    unsigned s2 = __float_as_uint(fmaxf(d[2], 0.f));
    unsigned s3 = __float_as_uint(fmaxf(d[3], 0.f));
    unsigned s4 = __float_as_uint(fmaxf(d[4], 0.f));
    unsigned s5 = __float_as_uint(fmaxf(d[5], 0.f));
    unsigned s6 = __float_as_uint(fmaxf(d[6], 0.f));
    unsigned s7 = __float_as_uint(fmaxf(d[7], 0.f));
    unsigned s8 = __float_as_uint(fmaxf(d[8], 0.f));
    CE(s0,s1) CE(s0,s2) CE(s0,s3) CE(s0,s4) CE(s0,s5) CE(s0,s6) CE(s0,s7) CE(s0,s8)
    CE(s1,s2) CE(s1,s3) CE(s1,s4) CE(s1,s5) CE(s1,s6) CE(s1,s7) CE(s1,s8)
    CE(s2,s3) CE(s2,s4) CE(s2,s5) CE(s2,s6) CE(s2,s7) CE(s2,s8)
    CE(s3,s4) CE(s3,s5) CE(s3,s6) CE(s3,s7) CE(s3,s8)
    CE(s4,s5) CE(s4,s6) CE(s4,s7) CE(s4,s8)
    CE(s5,s6) CE(s5,s7) CE(s5,s8)
    CE(s6,s7) CE(s6,s8)
    CE(s7,s8)

    float sumK = 0.f;
    unsigned need = KK;
    #pragma unroll 1
    while (need) {
        unsigned m = __reduce_min_sync(0xffffffffu, s0);
        bool hit = (s0 == m);
        unsigned tot = __reduce_add_sync(0xffffffffu, hit ? 1u : 0u);
        unsigned take = min(tot, need);
        sumK += __uint_as_float(m) * (float)take;
        need -= take;
        if (hit) {
            s0 = s1; s1 = s2; s2 = s3; s3 = s4;
            s4 = s5; s5 = s6; s6 = s7; s7 = s8;
            s8 = 0xffffffffu;
        }
    }
    if (lane == 0) atomicAdd(&g_accum, (double)sumK);

    /* ---- last-block finalize + reset ---- */
    __threadfence();
    __syncthreads();
    if (tid == 0) {
        unsigned prev = atomicAdd(&g_count, 1u);
        if (prev == gridDim.x - 1) {
            double s = atomicAdd(&g_accum, 0.0);
            float mean = (float)(s / ((double)NQ * (double)KK));
            for (int i = 0; i < out_size; i++) out[i] = mean;
            g_count = 0u;
            g_accum = 0.0;
            __threadfence();
        }
    }
}

extern "C" void kernel_launch(void* const* d_in, const int* in_sizes, int n_in,
                              void* d_out, int out_size) {
    const float* noisy = (const float*)d_in[0];
    /* d_in[1] = deno: dead */
    const float* fflow = (const float*)d_in[2];
    const float* bflow = (const float*)d_in[3];
    float* out = (float*)d_out;

    fused_kernel<<<NQ / WPB, 32 * WPB>>>(noisy, fflow, bflow, out, out_size);
}

// round 15
// speedup vs baseline: 1.0280x; 1.0280x over previous
#include <cuda_runtime.h>
#include <cuda_pipeline.h>
#include <math.h>
#include <float.h>

#define TT 5
#define CC 3
#define HH 384
#define WW 384
#define HW (HH*WW)
#define KK 10
#define NHH 96
#define NWW 96
#define NQ (TT*NHH*NWW)      /* 46080 */
#define WPB 4

/* private regions: rows [c0:16|c1:16|c2:16], row stride 52 floats (13 quads, odd) */
#define PRSTR 52
#define PCSTEP 16
#define PDI    780
/* shared di=1 region: rows [c0:28|c1:28|c2:28], stride 84 (21 quads, odd) */
#define SRSTR 84
#define SCSTEP 28
#define QSTR 8

typedef unsigned long long u64;

__device__ double       g_accum;
__device__ unsigned int g_count;

__device__ __forceinline__ void upk2(u64 v, float& lo, float& hi) {
    asm("mov.b64 {%0, %1}, %2;" : "=f"(lo), "=f"(hi) : "l"(v));
}
__device__ __forceinline__ void fma2(u64& d, u64 a, u64 b) {
    asm("fma.rn.f32x2 %0, %1, %2, %0;" : "+l"(d) : "l"(a), "l"(b));
}
#define CE(a,b) { unsigned lo_ = min(a,b), hi_ = max(a,b); a = lo_; b = hi_; }

__global__ void __launch_bounds__(32*WPB, 6)
fused_kernel(const float* __restrict__ vid,
             const float* __restrict__ fflow,
             const float* __restrict__ bflow,
             float* __restrict__ out, int out_size)
{
    __shared__ __align__(16) float s_region[WPB][2*PDI];   /* 6240B/warp */
    __shared__ __align__(16) float s_sh[15*SRSTR];         /* 5040B */
    __shared__ __align__(16) float s_qR[WPB][3*7*QSTR];    /* {q0..q6,0} */
    __shared__ __align__(16) float s_qL[WPB][3*7*QSTR];    /* {0,q0..q6} */
    __shared__ int   s_meta[WPB][12];

    const int tid  = threadIdx.x;
    const int warp = tid >> 5;
    const int lane = tid & 31;
    const int qidx = blockIdx.x * WPB + warp;

    const int ti = qidx / (NHH * NWW);
    const int rr = qidx - ti * (NHH * NWW);
    const int hi = (rr / NWW) * 4;
    const int wi = (rr % NWW) * 4;
    const int wi0 = wi - 4*warp;

    float* region = s_region[warp];
    float* qR     = s_qR[warp];
    float* qL     = s_qL[warp];
    int*   meta   = s_meta[warp];

    /* ---- meta per di (0: t-1/bflow, 1: t/zero, 2: t+1/fflow) ---- */
    if (lane < 3) {
        int di = lane;
        int tj, bh, bw;
        if (di == 1) { tj = ti; bh = hi; bw = wi; }
        else {
            const float* fl = (di == 0) ? bflow : fflow;
            tj = (di == 0) ? max(ti - 1, 0) : min(ti + 1, TT - 1);
            float fx = fl[((ti*2 + 0)*HH + hi)*WW + wi];
            float fy = fl[((ti*2 + 1)*HH + hi)*WW + wi];
            bh = min(max(hi + (int)rintf(fy), 0), HH - 1);
            bw = min(max(wi + (int)rintf(fx), 0), WW - 1);
        }
        meta[di*4 + 0] = tj;
        meta[di*4 + 1] = max(bh - 4, 0);
        meta[di*4 + 2] = bh;
        meta[di*4 + 3] = bw;
    }
    __syncwarp();

    /* ---- block-shared di=1 region: 15 rows x [3c x 28 cols]
           safe path: 16B cp.async (gmem base 16B-aligned: xsS mult of 4) ---- */
    {
        const int ysS = max(hi - 4, 0);
        const int xsS = max(wi0 - 4, 0);
        if (ysS <= HH-15 && xsS <= WW-28) {
            const float* src = vid + ti*3*HW + ysS*WW + xsS;
            if (tid < 105) {
                int row = tid / 7, ch = tid - (tid/7)*7;
                #pragma unroll
                for (int c = 0; c < 3; c++)
                    __pipeline_memcpy_async(s_sh + row*SRSTR + c*SCSTEP + ch*4,
                                            src + c*HW + row*WW + ch*4, 16);
            }
        } else {
            const int rx = tid & 31, r0 = tid >> 5;
            if (rx < 28) {
                #pragma unroll
                for (int c = 0; c < 3; c++) {
                    #pragma unroll
                    for (int k = 0; k < 4; k++) {
                        int r = r0 + 4*k;
                        if (r < 15) {
                            int y = min(ysS + r, HH-1);
                            int x = min(xsS + rx, WW-1);
                            s_sh[r*SRSTR + c*SCSTEP + rx] = vid[(ti*3 + c)*HW + y*WW + x];
                        }
                    }
                }
            }
        }
    }
    __pipeline_commit();   /* group A: s_sh */

    /* ---- per-warp regions di=0/di=2 (R10 lane map; safe path 4B cp.async) ---- */
    {
        const int ry = lane >> 4, rx = lane & 15;
        #pragma unroll
        for (int ds = 0; ds < 2; ds++) {
            const int di = ds*2;
            const int tj = meta[di*4 + 0];
            const int ys = meta[di*4 + 1];
            const int xs = max(meta[di*4 + 3] - 4, 0);
            float* dst0 = region + ds*PDI + ry*PRSTR + rx;
            if (ys <= HH-15 && xs <= WW-16) {
                const float* src0 = vid + tj*3*HW + (ys + ry)*WW + xs + rx;
                #pragma unroll
                for (int c = 0; c < 3; c++) {
                    const float* s2 = src0 + c*HW;
                    float* d2 = dst0 + c*PCSTEP;
                    #pragma unroll
                    for (int k = 0; k < 8; k++) {
                        if (ry + 2*k < 15)
                            __pipeline_memcpy_async(d2 + k*2*PRSTR, s2 + k*2*WW, 4);
                    }
                }
            } else {
                const float* src = vid + tj*3*HW;
                #pragma unroll
                for (int c = 0; c < 3; c++) {
                    #pragma unroll
                    for (int k = 0; k < 8; k++) {
                        int r = ry + 2*k;
                        if (r < 15) {
                            int y = min(ys + r, HH-1);
                            int x = min(xs + rx, WW-1);
                            region[ds*PDI + r*PRSTR + c*PCSTEP + rx] = src[c*HW + y*WW + x];
                        }
                    }
                }
            }
        }
    }
    __pipeline_commit();          /* group B: private */
    __pipeline_wait_prior(1);     /* s_sh complete */
    __syncthreads();              /* cross-warp visibility of s_sh */

    /* ---- query patch built from s_sh; Sum(q^2) (overlaps private staging) ---- */
    float qsq_part = 0.f;
    {
        const int rbase = min(hi, 4);
        const int cbase = wi - max(wi0 - 4, 0);
        #pragma unroll
        for (int k = 0; k < 6; k++) {
            int e = lane + 32*k;
            if (e < 168) {
                int row = e >> 3, px = e & 7;
                float val = 0.f;
                if (px < 7) {
                    int c = row / 7, py = row - (row/7)*7;
                    val = s_sh[(rbase + py)*SRSTR + c*SCSTEP + cbase + px];
                    qsq_part = fmaf(val, val, qsq_part);
                }
                qR[e] = val;
                qL[(row << 3) + ((px + 1) & 7)] = val;
            }
        }
    }
    #pragma unroll
    for (int off = 16; off; off >>= 1)
        qsq_part += __shfl_xor_sync(0xffffffffu, qsq_part, off);
    const float qs = qsq_part;
    __pipeline_wait_prior(0);     /* private regions complete (same-warp) */
    __syncwarp();

    float d[9];
    #pragma unroll
    for (int j = 0; j < 9; j++) d[j] = FLT_MAX;

    /* ---- lane remap: di-major groups of 8 -> phase-pure LDS.128 ---- */
    if (lane < 27) {
        const int di = (lane < 24) ? (lane >> 3) : (lane - 24);
        const int sy = (lane < 24) ? (lane & 7)  : 8;
        const int ys = meta[di*4 + 1];
        const int bh = meta[di*4 + 2];
        const int bw = meta[di*4 + 3];
        const int rowoff = min(max(bh - 4 + sy, 0), HH - 1) - ys;
        const int xsS = max(wi0 - 4, 0);
        const int xb  = (di == 1) ? xsS : max(bw - 4, 0);
        const int rstride = (di == 1) ? SRSTR : PRSTR;
        const int cstep   = (di == 1) ? SCSTEP : PCSTEP;
        const float* base = (di == 1) ? s_sh : region + (di == 0 ? 0 : PDI);
        const int xoff = max(bw - 4, 0) - xb;   /* 0 (private) or mult of 4 (di=1) */
        const bool fastx = (bw >= 4) && (bw <= WW - 11);

        if (fastx) {
            u64 acc[9], sq2[8];
            #pragma unroll
            for (int s = 0; s < 9; s++) acc[s] = 0ull;
            #pragma unroll
            for (int p = 0; p < 8; p++) sq2[p] = 0ull;

            const float* pb = base + rowoff*rstride + xoff;  /* 16B aligned */
            /* unroll 1: keep fast-path body ~6KB -> L0 I$-resident */
            #pragma unroll 1
            for (int c = 0; c < 3; c++) {
                #pragma unroll
                for (int py = 0; py < 7; py++) {
                    const ulonglong2* vr = (const ulonglong2*)(pb + py*rstride + c*cstep);
                    ulonglong2 va = vr[0], vb = vr[1], vc = vr[2], vd = vr[3];
                    u64 ve[8] = {va.x, va.y, vb.x, vb.y, vc.x, vc.y, vd.x, vd.y};
                    const ulonglong2* qrv = (const ulonglong2*)(qR + (c*7 + py)*QSTR);
                    const ulonglong2* qlv = (const ulonglong2*)(qL + (c*7 + py)*QSTR);
                    ulonglong2 qa = qrv[0], qb = qrv[1];
                    ulonglong2 qc = qlv[0], qd = qlv[1];
                    u64 qe[4] = {qa.x, qa.y, qb.x, qb.y};
                    u64 qo[4] = {qc.x, qc.y, qd.x, qd.y};

                    #pragma unroll
                    for (int j = 0; j < 4; j++) {
                        #pragma unroll
                        for (int e2 = 0; e2 < 5; e2++)      /* sx = 0,2,4,6,8 */
                            fma2(acc[2*e2], qe[j], ve[e2 + j]);
                        #pragma unroll
                        for (int o = 0; o < 4; o++)         /* sx = 1,3,5,7 */
                            fma2(acc[2*o + 1], qo[j], ve[o + j]);
                    }
                    #pragma unroll
                    for (int p = 0; p < 8; p++) fma2(sq2[p], ve[p], ve[p]);
                }
            }

            float col[15];
            {
                float lo, hiv;
                #pragma unroll
                for (int p = 0; p < 7; p++) { upk2(sq2[p], lo, hiv); col[2*p] = lo; col[2*p+1] = hiv; }
                upk2(sq2[7], lo, hiv); col[14] = lo;
            }
            float pre[16]; pre[0] = 0.f;
            #pragma unroll
            for (int j = 0; j < 15; j++) pre[j+1] = pre[j] + col[j];
            #pragma unroll
            for (int sx = 0; sx < 9; sx++) {
                float alo, ahi; upk2(acc[sx], alo, ahi);
                float qv2 = alo + ahi;
                float vs = pre[sx+7] - pre[sx];
                d[sx] = fmaf(-2.f, qv2, qs + vs);
            }
        } else {
            /* rare x-border path */
            #pragma unroll
            for (int sx = 0; sx < 9; sx++) {
                int co = min(max(bw - 4 + sx, 0), WW - 1) - xb;
                float a = 0.f;
                for (int c = 0; c < 3; c++) {
                    for (int py = 0; py < 7; py++) {
                        const float* row = base + (rowoff + py)*rstride + c*cstep + co;
                        const float* qrow = qR + (c*7 + py)*QSTR;
                        #pragma unroll
                        for (int px = 0; px < 7; px++) {
                            float t = qrow[px] - row[px];
                            a = fmaf(t, t, a);
                        }
                    }
                }
                d[sx] = a;
            }
        }
    }

    /* ---- top-10: per-lane selection-sort network + shift-advance extract ---- */
    unsigned s0 = __float_as_uint(fmaxf(d[0], 0.f));
    unsigned s1 = __float_as_uint(fmaxf(d[1], 0.f));
    unsigned s2 = __float_as_uint(fmaxf(d[2], 0.f));
    unsigned s3 = __float_as_uint(fmaxf(d[3], 0.f));
    unsigned s4 = __float_as_uint(fmaxf(d[4], 0.f));
    unsigned s5 = __float_as_uint(fmaxf(d[5], 0.f));
    unsigned s6 = __float_as_uint(fmaxf(d[6], 0.f));
    unsigned s7 = __float_as_uint(fmaxf(d[7], 0.f));
    unsigned s8 = __float_as_uint(fmaxf(d[8], 0.f));
    CE(s0,s1) CE(s0,s2) CE(s0,s3) CE(s0,s4) CE(s0,s5) CE(s0,s6) CE(s0,s7) CE(s0,s8)
    CE(s1,s2) CE(s1,s3) CE(s1,s4) CE(s1,s5) CE(s1,s6) CE(s1,s7) CE(s1,s8)
    CE(s2,s3) CE(s2,s4) CE(s2,s5) CE(s2,s6) CE(s2,s7) CE(s2,s8)
    CE(s3,s4) CE(s3,s5) CE(s3,s6) CE(s3,s7) CE(s3,s8)
    CE(s4,s5) CE(s4,s6) CE(s4,s7) CE(s4,s8)
    CE(s5,s6) CE(s5,s7) CE(s5,s8)
    CE(s6,s7) CE(s6,s8)
    CE(s7,s8)

    float sumK = 0.f;
    unsigned need = KK;
    #pragma unroll 1
    while (need) {
        unsigned m = __reduce_min_sync(0xffffffffu, s0);
        bool hit = (s0 == m);
        unsigned tot = __popc(__ballot_sync(0xffffffffu, hit));
        unsigned take = min(tot, need);
        sumK += __uint_as_float(m) * (float)take;
        need -= take;
        if (hit) {
            s0 = s1; s1 = s2; s2 = s3; s3 = s4;
            s4 = s5; s5 = s6; s6 = s7; s7 = s8;
            s8 = 0xffffffffu;
        }
    }
    if (lane == 0) atomicAdd(&g_accum, (double)sumK);

    /* ---- last-block finalize + reset ---- */
    __threadfence();
    __syncthreads();
    if (tid == 0) {
        unsigned prev = atomicAdd(&g_count, 1u);
        if (prev == gridDim.x - 1) {
            double s = atomicAdd(&g_accum, 0.0);
            float mean = (float)(s / ((double)NQ * (double)KK));
            for (int i = 0; i < out_size; i++) out[i] = mean;
            g_count = 0u;
            g_accum = 0.0;
            __threadfence();
        }
    }
}

extern "C" void kernel_launch(void* const* d_in, const int* in_sizes, int n_in,
                              void* d_out, int out_size) {
    const float* noisy = (const float*)d_in[0];
    /* d_in[1] = deno: dead */
    const float* fflow = (const float*)d_in[2];
    const float* bflow = (const float*)d_in[3];
    float* out = (float*)d_out;

    fused_kernel<<<NQ / WPB, 32 * WPB>>>(noisy, fflow, bflow, out, out_size);
}